// round 4
// baseline (speedup 1.0000x reference)
#include <cuda_runtime.h>
#include <cstdint>

// LRAP loss, B x C = 16384 x 2048.
// Bucket-counting rank computation (no sort). 32-bit keys, atomic-return
// scatter offsets (no cursor atomics), in-place packed prefix scan,
// per-bucket O(cnt^2) residual rank resolution.

#define NCLS    2048
#define THREADS 512
#define NWARP   (THREADS / 32)   // 16

__device__ double g_rowscore[16384];

__device__ __forceinline__ uint32_t orderFloat(float f) {
    uint32_t u = __float_as_uint(f);
    return (u & 0x80000000u) ? ~u : (u | 0x80000000u);  // monotone increasing
}

__global__ __launch_bounds__(THREADS)
void lrap_row_kernel(const float* __restrict__ preds,
                     const float* __restrict__ labels) {
    const int row = blockIdx.x;
    const int t   = threadIdx.x;

    __shared__ uint32_t bins[NCLS];   // pass1: packed hist (lo16 cnt, hi16 pos)
                                      // pass2: packed exclusive prefix
    __shared__ uint32_t scat[NCLS];   // bucket-grouped 32-bit keys
    __shared__ uint32_t warpSums[NWARP];
    __shared__ double   redS[NWARP];
    __shared__ int      redN[NWARP];

    // ---- zero histogram (one STS.128 per thread) ----
    *(uint4*)&bins[t * 4] = make_uint4(0u, 0u, 0u, 0u);
    __syncthreads();

    // ---- phase A: load one float4 of preds+labels, bin, histogram ----
    const float4 pv = ((const float4*)(preds  + (size_t)row * NCLS))[t];
    const float4 lv = ((const float4*)(labels + (size_t)row * NCLS))[t];
    const float px[4] = {pv.x, pv.y, pv.z, pv.w};
    const float lx[4] = {lv.x, lv.y, lv.z, lv.w};

    uint32_t key[4];    // (orderFloat & ~1) | label
    uint32_t combo[4];  // (bucket << 16) | within-bucket offset
    uint32_t labm = 0;

    #pragma unroll
    for (int c = 0; c < 4; c++) {
        uint32_t lab = (lx[c] > 0.5f) ? 1u : 0u;
        labm |= lab << c;
        key[c] = (orderFloat(px[c]) & 0xFFFFFFFEu) | lab;
        int bin = __float2int_rd(fmaf(px[c], 256.0f, 1024.0f));
        bin = max(0, min(2047, bin));
        int b = 2047 - bin;             // bucket 0 = largest preds = best ranks
        uint32_t old = atomicAdd(&bins[b], 1u + (lab << 16));
        combo[c] = ((uint32_t)b << 16) | (old & 0xFFFFu);
    }
    __syncthreads();

    // ---- phase B: in-place packed exclusive prefix over 2048 counters ----
    uint32_t loc[4];
    uint32_t s = 0;
    const uint4 hv = *(const uint4*)&bins[t * 4];
    const uint32_t h[4] = {hv.x, hv.y, hv.z, hv.w};
    #pragma unroll
    for (int c = 0; c < 4; c++) { loc[c] = s; s += h[c]; }

    uint32_t inc = s;
    const int lane = t & 31, wid = t >> 5;
    #pragma unroll
    for (int off = 1; off < 32; off <<= 1) {
        uint32_t n = __shfl_up_sync(0xffffffffu, inc, off);
        if (lane >= off) inc += n;
    }
    if (lane == 31) warpSums[wid] = inc;
    __syncthreads();
    if (t == 0) {
        uint32_t acc = 0;
        #pragma unroll
        for (int w = 0; w < NWARP; w++) { uint32_t v = warpSums[w]; warpSums[w] = acc; acc += v; }
    }
    __syncthreads();
    const uint32_t exclT = warpSums[wid] + (inc - s);
    *(uint4*)&bins[t * 4] = make_uint4(exclT + loc[0], exclT + loc[1],
                                       exclT + loc[2], exclT + loc[3]);
    __syncthreads();

    // ---- phase C: scatter keys (no atomics: offset came from phase A) ----
    #pragma unroll
    for (int c = 0; c < 4; c++) {
        uint32_t b   = combo[c] >> 16;
        uint32_t off = combo[c] & 0xFFFFu;
        scat[(bins[b] & 0xFFFFu) + off] = key[c];
    }
    __syncthreads();

    // ---- phase D: per-bucket exact ranks for positives ----
    float sc = 0.0f;
    int npos = __popc(labm);
    #pragma unroll
    for (int c = 0; c < 4; c++) {
        uint32_t ps = exclT + loc[c];
        uint32_t pe = (c < 3) ? (exclT + loc[c + 1]) : (exclT + s);
        uint32_t st = ps & 0xFFFFu;
        uint32_t en = pe & 0xFFFFu;
        uint32_t pB = ps >> 16;           // positives in strictly-better buckets
        for (uint32_t m = st; m < en; m++) {
            uint32_t k = scat[m];
            if (k & 1u) {
                uint32_t gt = 0, pg = 0;
                for (uint32_t n = st; n < en; n++) {
                    uint32_t k2 = scat[n];
                    if (k2 > k) { gt++; pg += (k2 & 1u); }
                }
                sc += __fdividef((float)(pB + pg + 1u), (float)(st + gt + 1u));
            }
        }
    }

    // ---- phase E: block reduce, per-row score ----
    double d = (double)sc;
    #pragma unroll
    for (int off = 16; off; off >>= 1) {
        d    += __shfl_down_sync(0xffffffffu, d, off);
        npos += __shfl_down_sync(0xffffffffu, npos, off);
    }
    if (lane == 0) { redS[wid] = d; redN[wid] = npos; }
    __syncthreads();
    if (t == 0) {
        double tot = 0.0; int np = 0;
        #pragma unroll
        for (int w = 0; w < NWARP; w++) { tot += redS[w]; np += redN[w]; }
        g_rowscore[row] = tot / (double)np;
    }
}

__global__ __launch_bounds__(1024)
void lrap_reduce_kernel(float* __restrict__ out, int B) {
    __shared__ double red[32];
    const int t = threadIdx.x;
    double a0 = 0.0, a1 = 0.0, a2 = 0.0, a3 = 0.0;
    int i = t;
    for (; i + 3 * 1024 < B; i += 4096) {
        a0 += g_rowscore[i];
        a1 += g_rowscore[i + 1024];
        a2 += g_rowscore[i + 2048];
        a3 += g_rowscore[i + 3072];
    }
    for (; i < B; i += 1024) a0 += g_rowscore[i];
    double s = (a0 + a1) + (a2 + a3);

    const int lane = t & 31, wid = t >> 5;
    #pragma unroll
    for (int off = 16; off; off >>= 1) s += __shfl_down_sync(0xffffffffu, s, off);
    if (lane == 0) red[wid] = s;
    __syncthreads();
    if (t == 0) {
        double tot = 0.0;
        for (int w = 0; w < 32; w++) tot += red[w];
        out[0] = (float)(tot / (double)B);
    }
}

extern "C" void kernel_launch(void* const* d_in, const int* in_sizes, int n_in,
                              void* d_out, int out_size) {
    const float* preds  = (const float*)d_in[0];
    const float* labels = (const float*)d_in[1];
    float* out = (float*)d_out;

    int B = in_sizes[0] / NCLS;
    if (B > 16384) B = 16384;   // scratch capacity

    lrap_row_kernel<<<B, THREADS>>>(preds, labels);
    lrap_reduce_kernel<<<1, 1024>>>(out, B);
}